// round 15
// baseline (speedup 1.0000x reference)
#include <cuda_runtime.h>
#include <cuda_bf16.h>

#define BB 64
#define SS 512
#define EE 512
#define HD 1024
#define NO 10
#define NBLK 128
#define GTHR 512

typedef unsigned long long ull;
typedef __nv_bfloat16 bf16;

// -------- scratch --------
__device__ float g_xproj[(size_t)SS * BB * 3 * HD];
__device__ float g_H[2][HD * BB];                 // fp32 [k][b]
__device__ bf16  g_Hbf[2][2][BB][HD];             // [parity][hi/lo][b][k]
__device__ bf16  g_Hrbf[2][2][BB][HD];            // [s&1][hi/lo][b][k]
__device__ unsigned g_arrive[NBLK * 32];
__device__ unsigned g_F1[NBLK * 32];
__device__ unsigned g_F2[NBLK * 32];
__device__ bf16 g_wt[3][2][HD][EE];               // proj W [gate][h][n][k]
__device__ bf16 g_wrt[3][2][HD][HD];              // recur W [gate][h][n][k]

// -------- helpers --------
__device__ __forceinline__ float sigmoid_f(float x) { return 1.0f / (1.0f + __expf(-x)); }
__device__ __forceinline__ float tanh_f(float x) {
    float ax = fabsf(x), t = __expf(-2.0f * ax);
    return copysignf(__fdividef(1.0f - t, 1.0f + t), x);
}
__device__ __forceinline__ float ldcg_f(const float* p) {
    float v; asm("ld.global.cg.f32 %0, [%1];" : "=f"(v) : "l"(p)); return v;
}
__device__ __forceinline__ void st_hilo(bf16* hi, bf16* lo, float a, float b) {
    bf16 h0 = __float2bfloat16_rn(a), h1 = __float2bfloat16_rn(b);
    __nv_bfloat162 H; H.x = h0; H.y = h1;
    *(__nv_bfloat162*)hi = H;
    __nv_bfloat162 L;
    L.x = __float2bfloat16_rn(a - __bfloat162float(h0));
    L.y = __float2bfloat16_rn(b - __bfloat162float(h1));
    *(__nv_bfloat162*)lo = L;
}
__device__ __forceinline__ void ldsm_x4(unsigned& r0, unsigned& r1, unsigned& r2,
                                        unsigned& r3, unsigned addr) {
    asm volatile("ldmatrix.sync.aligned.m8n8.x4.shared.b16 {%0,%1,%2,%3}, [%4];"
                 : "=r"(r0), "=r"(r1), "=r"(r2), "=r"(r3) : "r"(addr));
}
__device__ __forceinline__ void ldsm_x2(unsigned& r0, unsigned& r1, unsigned addr) {
    asm volatile("ldmatrix.sync.aligned.m8n8.x2.shared.b16 {%0,%1}, [%2];"
                 : "=r"(r0), "=r"(r1) : "r"(addr));
}
__device__ __forceinline__ void mma_bf16(float* c, const unsigned* a,
                                         unsigned b0, unsigned b1) {
    asm volatile(
        "mma.sync.aligned.m16n8k16.row.col.f32.bf16.bf16.f32 "
        "{%0,%1,%2,%3},{%4,%5,%6,%7},{%8,%9},{%0,%1,%2,%3};"
        : "+f"(c[0]), "+f"(c[1]), "+f"(c[2]), "+f"(c[3])
        : "r"(a[0]), "r"(a[1]), "r"(a[2]), "r"(a[3]), "r"(b0), "r"(b1));
}
__device__ __forceinline__ void publish(unsigned* slot, unsigned val) {
    asm volatile("st.release.gpu.u32 [%0], %1;" :: "l"(slot), "r"(val) : "memory");
}
__device__ __forceinline__ void poll_flag(const unsigned* p, unsigned target) {
    unsigned v;
    for (;;) {
        asm volatile("ld.relaxed.gpu.u32 %0, [%1];" : "=r"(v) : "l"(p) : "memory");
        if (v >= target) break;
        __nanosleep(20);
    }
    asm volatile("ld.acquire.gpu.u32 %0, [%1];" : "=r"(v) : "l"(p) : "memory");
}
__device__ __forceinline__ void flat_barrier(unsigned target, int bx) {
    __syncthreads();
    if (threadIdx.x == 0) {
        __threadfence();
        publish(&g_arrive[bx * 32], target);
    }
    if (threadIdx.x < NBLK) {
        const unsigned* p = &g_arrive[threadIdx.x * 32];
        unsigned v;
        do {
            asm volatile("ld.acquire.gpu.u32 %0, [%1];" : "=r"(v) : "l"(p) : "memory");
        } while (v < target);
    }
    __syncthreads();
}

__global__ void reset_kernel() {
    int t = threadIdx.x;
    for (int i = t; i < NBLK * 32; i += blockDim.x) {
        g_arrive[i] = 0u; g_F1[i] = 0u; g_F2[i] = 0u;
    }
}

// ---- weight converts ----
__global__ __launch_bounds__(256) void wconv_kernel(
    const float* __restrict__ Wxr, const float* __restrict__ Wxz,
    const float* __restrict__ Wxc) {
    const int k = blockIdx.x, gate = blockIdx.y;
    const float* W = (gate == 0) ? Wxr : ((gate == 1) ? Wxz : Wxc);
    const int n0 = threadIdx.x * 4;
    float4 v = *(const float4*)(W + (size_t)k * HD + n0);
    float xs[4] = {v.x, v.y, v.z, v.w};
#pragma unroll
    for (int i = 0; i < 4; i++) {
        bf16 h = __float2bfloat16_rn(xs[i]);
        g_wt[gate][0][n0 + i][k] = h;
        g_wt[gate][1][n0 + i][k] = __float2bfloat16_rn(xs[i] - __bfloat162float(h));
    }
}
__global__ __launch_bounds__(256) void wrconv_kernel(
    const float* __restrict__ Whr, const float* __restrict__ Whz,
    const float* __restrict__ Whc) {
    const int k = blockIdx.x, gate = blockIdx.y;
    const float* W = (gate == 0) ? Whr : ((gate == 1) ? Whz : Whc);
    const int n0 = threadIdx.x * 4;
    float4 v = *(const float4*)(W + (size_t)k * HD + n0);
    float xs[4] = {v.x, v.y, v.z, v.w};
#pragma unroll
    for (int i = 0; i < 4; i++) {
        bf16 h = __float2bfloat16_rn(xs[i]);
        g_wrt[gate][0][n0 + i][k] = h;
        g_wrt[gate][1][n0 + i][k] = __float2bfloat16_rn(xs[i] - __bfloat162float(h));
    }
}

// =====================================================================
// Kernel 1: proj via split-bf16 mma (R13, proven)
// =====================================================================
__global__ __launch_bounds__(256) void proj_kernel(
    const int* __restrict__ inputs, const float* __restrict__ emb,
    const float* __restrict__ br, const float* __restrict__ bz,
    const float* __restrict__ bc) {
    __shared__ __align__(16) bf16 Ahi[64][72], Alo[64][72];
    __shared__ __align__(16) bf16 Bhi[64][72], Blo[64][72];
    __shared__ int tok[64];

    const int s = blockIdx.y, nt = blockIdx.x;
    const int gate = nt >> 4, gc0 = (nt & 15) * 64;
    const float* bias = (gate == 0) ? br : ((gate == 1) ? bz : bc);
    const int tid = threadIdx.x, w = tid >> 5, lane = tid & 31;
    const int m0w = (w & 3) * 16, n0w = (w >> 2) * 32;

    if (tid < 64) tok[tid] = inputs[tid * SS + s];
    __syncthreads();

    const int am = tid >> 2, akq = (tid & 3) * 16;
    const int bh = tid >> 7, bn = (tid & 127) >> 1, bkq = (tid & 1) * 32;
    const float* arow = emb + (size_t)tok[am] * EE + akq;
    const bf16* bsrc = &g_wt[gate][bh][gc0 + bn][0] + bkq;

    unsigned a_hi_base = (unsigned)__cvta_generic_to_shared(
        &Ahi[m0w + (lane & 7) + ((lane >> 3) & 1) * 8][((lane >> 4) & 1) * 8]);
    unsigned a_lo_base = (unsigned)__cvta_generic_to_shared(
        &Alo[m0w + (lane & 7) + ((lane >> 3) & 1) * 8][((lane >> 4) & 1) * 8]);
    const int brow = ((lane >> 4) & 1) * 8 + (lane & 7);
    const int bcol = ((lane >> 3) & 1) * 8;
    unsigned b_hi0 = (unsigned)__cvta_generic_to_shared(&Bhi[n0w + brow][bcol]);
    unsigned b_hi1 = (unsigned)__cvta_generic_to_shared(&Bhi[n0w + 16 + brow][bcol]);
    unsigned b_lo0 = (unsigned)__cvta_generic_to_shared(&Blo[n0w + brow][bcol]);
    unsigned b_lo1 = (unsigned)__cvta_generic_to_shared(&Blo[n0w + 16 + brow][bcol]);

    float acc[4][4];
#pragma unroll
    for (int a = 0; a < 4; a++)
#pragma unroll
        for (int i = 0; i < 4; i++) acc[a][i] = 0.f;

    float a_reg[16];
    uint4 b_reg[4];
    *(float4*)(a_reg + 0)  = *(const float4*)(arow + 0);
    *(float4*)(a_reg + 4)  = *(const float4*)(arow + 4);
    *(float4*)(a_reg + 8)  = *(const float4*)(arow + 8);
    *(float4*)(a_reg + 12) = *(const float4*)(arow + 12);
    b_reg[0] = *(const uint4*)(bsrc);
    b_reg[1] = *(const uint4*)(bsrc + 8);
    b_reg[2] = *(const uint4*)(bsrc + 16);
    b_reg[3] = *(const uint4*)(bsrc + 24);

#pragma unroll 1
    for (int c = 0; c < 8; ++c) {
#pragma unroll
        for (int i = 0; i < 16; i += 2) {
            float x0 = a_reg[i], x1 = a_reg[i + 1];
            st_hilo(&Ahi[am][akq + i], &Alo[am][akq + i], x0, x1);
        }
        {
            bf16 (*Bd)[72] = bh ? Blo : Bhi;
            *(uint4*)&Bd[bn][bkq]      = b_reg[0];
            *(uint4*)&Bd[bn][bkq + 8]  = b_reg[1];
            *(uint4*)&Bd[bn][bkq + 16] = b_reg[2];
            *(uint4*)&Bd[bn][bkq + 24] = b_reg[3];
        }
        __syncthreads();
        if (c < 7) {
            const float* an = arow + (c + 1) * 64;
            *(float4*)(a_reg + 0)  = *(const float4*)(an + 0);
            *(float4*)(a_reg + 4)  = *(const float4*)(an + 4);
            *(float4*)(a_reg + 8)  = *(const float4*)(an + 8);
            *(float4*)(a_reg + 12) = *(const float4*)(an + 12);
            const bf16* bnp = bsrc + (c + 1) * 64;
            b_reg[0] = *(const uint4*)(bnp);
            b_reg[1] = *(const uint4*)(bnp + 8);
            b_reg[2] = *(const uint4*)(bnp + 16);
            b_reg[3] = *(const uint4*)(bnp + 24);
        }
#pragma unroll
        for (int ks = 0; ks < 4; ++ks) {
            const unsigned off = ks * 32;
            unsigned ah[4], al[4], h0[4], h1[4], l0[4], l1[4];
            ldsm_x4(ah[0], ah[1], ah[2], ah[3], a_hi_base + off);
            ldsm_x4(al[0], al[1], al[2], al[3], a_lo_base + off);
            ldsm_x4(h0[0], h0[1], h0[2], h0[3], b_hi0 + off);
            ldsm_x4(h1[0], h1[1], h1[2], h1[3], b_hi1 + off);
            ldsm_x4(l0[0], l0[1], l0[2], l0[3], b_lo0 + off);
            ldsm_x4(l1[0], l1[1], l1[2], l1[3], b_lo1 + off);
            mma_bf16(acc[0], ah, h0[0], h0[1]);
            mma_bf16(acc[0], ah, l0[0], l0[1]);
            mma_bf16(acc[0], al, h0[0], h0[1]);
            mma_bf16(acc[1], ah, h0[2], h0[3]);
            mma_bf16(acc[1], ah, l0[2], l0[3]);
            mma_bf16(acc[1], al, h0[2], h0[3]);
            mma_bf16(acc[2], ah, h1[0], h1[1]);
            mma_bf16(acc[2], ah, l1[0], l1[1]);
            mma_bf16(acc[2], al, h1[0], h1[1]);
            mma_bf16(acc[3], ah, h1[2], h1[3]);
            mma_bf16(acc[3], ah, l1[2], l1[3]);
            mma_bf16(acc[3], al, h1[2], h1[3]);
        }
        __syncthreads();
    }
    const int row0 = m0w + (lane >> 2);
#pragma unroll
    for (int a = 0; a < 4; a++) {
        const int col = gc0 + n0w + a * 8 + 2 * (lane & 3);
        float2 bi = *(const float2*)(bias + col);
        float2 v0 = make_float2(acc[a][0] + bi.x, acc[a][1] + bi.y);
        float2 v1 = make_float2(acc[a][2] + bi.x, acc[a][3] + bi.y);
        float* base = g_xproj + ((size_t)s * BB + row0) * (3 * HD) + gate * HD + col;
        __stcs((float2*)base, v0);
        __stcs((float2*)(base + 8 * 3 * HD), v1);
    }
}

// =====================================================================
// Kernel 2: MMA GRU. 128 blocks x 512 threads. smem-resident weights.
// =====================================================================
#define ASTR 136
#define BSTR 1032
#define ALO_OFF (64 * ASTR)
#define B1_OFF  (2 * 64 * ASTR)
#define B2_OFF  (B1_OFF + 2 * 16 * BSTR)
#define GSM_BF  (B2_OFF + 2 * 8 * BSTR)
#define GRU_SMEM (GSM_BF * 2)

__global__ __launch_bounds__(GTHR, 1) void gru_kernel() {
    extern __shared__ __align__(16) bf16 sm[];
    bf16* A_hi = sm;
    bf16* A_lo = sm + ALO_OFF;
    __shared__ float red[12 * 128];
    __shared__ float zsm[8 * 64];

    const int tid = threadIdx.x, bx = blockIdx.x;
    const int w = tid >> 5, lane = tid & 31;
    const int colb = bx * 8;

    // zero H0 (fp32 + bf16) each launch
    for (int i = bx * GTHR + tid; i < HD * BB / 4; i += NBLK * GTHR)
        ((float4*)g_H[0])[i] = make_float4(0.f, 0.f, 0.f, 0.f);
    for (int i = bx * GTHR + tid; i < 2 * BB * HD / 8; i += NBLK * GTHR)
        ((uint4*)g_Hbf[0])[i] = make_uint4(0, 0, 0, 0);
    flat_barrier(1, bx);

    // load resident weights: B1 (r,z: 16 rows) + B2 (c: 8 rows)
    for (int g = tid; g < 4096; g += GTHR) {   // B1: 2h*16n*128 groups of 8
        int h = g >> 11, n = (g >> 7) & 15, kq = (g & 127) * 8;
        *(uint4*)&sm[B1_OFF + (h * 16 + n) * BSTR + kq] =
            *(const uint4*)&g_wrt[n >> 3][h][colb + (n & 7)][kq];
    }
    for (int g = tid; g < 2048; g += GTHR) {   // B2
        int h = g >> 10, n = (g >> 7) & 7, kq = (g & 127) * 8;
        *(uint4*)&sm[B2_OFF + (h * 8 + n) * BSTR + kq] =
            *(const uint4*)&g_wrt[2][h][colb + n][kq];
    }
    __syncthreads();

    // per-warp decode
    const int mt = w & 3;
    const int nt1 = (w >> 2) & 1, kh1 = w >> 3;      // phase 1
    const int kq2 = w >> 2;                          // phase 2 k-quarter
    unsigned a_hi_b = (unsigned)__cvta_generic_to_shared(
        &A_hi[(mt * 16 + (lane & 7) + ((lane >> 3) & 1) * 8) * ASTR + ((lane >> 4) & 1) * 8]);
    unsigned a_lo_b = a_hi_b + ALO_OFF * 2;
    const int bl = lane & 15;
    unsigned b1h = (unsigned)__cvta_generic_to_shared(
        &sm[B1_OFF + (nt1 * 8 + (bl & 7)) * BSTR + ((bl >> 3) & 1) * 8]);
    unsigned b1l = b1h + 16 * BSTR * 2;
    unsigned b2h = (unsigned)__cvta_generic_to_shared(
        &sm[B2_OFF + (bl & 7) * BSTR + ((bl >> 3) & 1) * 8]);
    unsigned b2l = b2h + 8 * BSTR * 2;
    const int er = (lane >> 2);                       // epilogue row-in-tile
    const int ej = 2 * (lane & 3);                    // epilogue col pair

    int p = 0;
#pragma unroll 1
    for (int s = 0; s < SS; ++s) {
        const float* xpg = g_xproj + (size_t)s * BB * 3 * HD;
        const int par = s & 1;

        // ---------- phase 1 ----------
        float acc1[4] = {0.f, 0.f, 0.f, 0.f};
#pragma unroll 1
        for (int c = 0; c < 8; ++c) {
            if (tid < 16) poll_flag(&g_F2[(c * 16 + tid) * 32], (unsigned)s);
            __syncthreads();
            {
                int b = tid >> 3, kq = (tid & 7) * 16;
                const bf16* sh = &g_Hbf[p][0][b][c * 128 + kq];
                const bf16* sl = &g_Hbf[p][1][b][c * 128 + kq];
                *(uint4*)&A_hi[b * ASTR + kq]     = *(const uint4*)sh;
                *(uint4*)&A_hi[b * ASTR + kq + 8] = *(const uint4*)(sh + 8);
                *(uint4*)&A_lo[b * ASTR + kq]     = *(const uint4*)sl;
                *(uint4*)&A_lo[b * ASTR + kq + 8] = *(const uint4*)(sl + 8);
            }
            __syncthreads();
#pragma unroll
            for (int ks = 0; ks < 4; ++ks) {
                unsigned aoff = (kh1 * 64 + ks * 16) * 2;
                unsigned boff = (c * 128 + kh1 * 64 + ks * 16) * 2;
                unsigned ah[4], al[4], bh0, bh1, bl0, bl1;
                ldsm_x4(ah[0], ah[1], ah[2], ah[3], a_hi_b + aoff);
                ldsm_x4(al[0], al[1], al[2], al[3], a_lo_b + aoff);
                ldsm_x2(bh0, bh1, b1h + boff);
                ldsm_x2(bl0, bl1, b1l + boff);
                mma_bf16(acc1, ah, bh0, bh1);
                mma_bf16(acc1, ah, bl0, bl1);
                mma_bf16(acc1, al, bh0, bh1);
            }
        }
        if (w >= 8) *(float4*)&red[((w - 8) * 32 + lane) * 4] = *(float4*)acc1;
        __syncthreads();
        if (w < 8) {
            float4 o = *(float4*)&red[(w * 32 + lane) * 4];
            acc1[0] += o.x; acc1[1] += o.y; acc1[2] += o.z; acc1[3] += o.w;
            const int r0 = mt * 16 + er;
            float2 xa = __ldcs((const float2*)(xpg + r0 * 3 * HD + nt1 * HD + colb + ej));
            float2 xb = __ldcs((const float2*)(xpg + (r0 + 8) * 3 * HD + nt1 * HD + colb + ej));
            float v0 = sigmoid_f(acc1[0] + xa.x), v1 = sigmoid_f(acc1[1] + xa.y);
            float v2 = sigmoid_f(acc1[2] + xb.x), v3 = sigmoid_f(acc1[3] + xb.y);
            if (nt1 == 0) {
                const float* Hc = g_H[p];
                float h00 = ldcg_f(Hc + (colb + ej) * BB + r0);
                float h01 = ldcg_f(Hc + (colb + ej + 1) * BB + r0);
                float h10 = ldcg_f(Hc + (colb + ej) * BB + r0 + 8);
                float h11 = ldcg_f(Hc + (colb + ej + 1) * BB + r0 + 8);
                st_hilo(&g_Hrbf[par][0][r0][colb + ej], &g_Hrbf[par][1][r0][colb + ej],
                        h00 * v0, h01 * v1);
                st_hilo(&g_Hrbf[par][0][r0 + 8][colb + ej], &g_Hrbf[par][1][r0 + 8][colb + ej],
                        h10 * v2, h11 * v3);
            } else {
                zsm[ej * 64 + r0] = v0; zsm[(ej + 1) * 64 + r0] = v1;
                zsm[ej * 64 + r0 + 8] = v2; zsm[(ej + 1) * 64 + r0 + 8] = v3;
            }
        }
        __syncthreads();
        if (tid == 0) { __threadfence(); publish(&g_F1[bx * 32], (unsigned)(s + 1)); }

        // ---------- phase 2 ----------
        float acc2[4] = {0.f, 0.f, 0.f, 0.f};
#pragma unroll 1
        for (int c = 0; c < 8; ++c) {
            if (tid < 16) poll_flag(&g_F1[(c * 16 + tid) * 32], (unsigned)(s + 1));
            __syncthreads();
            {
                int b = tid >> 3, kq = (tid & 7) * 16;
                const bf16* sh = &g_Hrbf[par][0][b][c * 128 + kq];
                const bf16* sl = &g_Hrbf[par][1][b][c * 128 + kq];
                *(uint4*)&A_hi[b * ASTR + kq]     = *(const uint4*)sh;
                *(uint4*)&A_hi[b * ASTR + kq + 8] = *(const uint4*)(sh + 8);
                *(uint4*)&A_lo[b * ASTR + kq]     = *(const uint4*)sl;
                *(uint4*)&A_lo[b * ASTR + kq + 8] = *(const uint4*)(sl + 8);
            }
            __syncthreads();
#pragma unroll
            for (int ks = 0; ks < 2; ++ks) {
                unsigned aoff = (kq2 * 32 + ks * 16) * 2;
                unsigned boff = (c * 128 + kq2 * 32 + ks * 16) * 2;
                unsigned ah[4], al[4], bh0, bh1, bl0, bl1;
                ldsm_x4(ah[0], ah[1], ah[2], ah[3], a_hi_b + aoff);
                ldsm_x4(al[0], al[1], al[2], al[3], a_lo_b + aoff);
                ldsm_x2(bh0, bh1, b2h + boff);
                ldsm_x2(bl0, bl1, b2l + boff);
                mma_bf16(acc2, ah, bh0, bh1);
                mma_bf16(acc2, ah, bl0, bl1);
                mma_bf16(acc2, al, bh0, bh1);
            }
        }
        if (w >= 4) *(float4*)&red[((w - 4) * 32 + lane) * 4] = *(float4*)acc2;
        __syncthreads();
        if (w < 4) {
#pragma unroll
            for (int q = 0; q < 3; ++q) {
                float4 o = *(float4*)&red[((q * 4 + w) * 32 + lane) * 4];
                acc2[0] += o.x; acc2[1] += o.y; acc2[2] += o.z; acc2[3] += o.w;
            }
            const int r0 = mt * 16 + er;
            float2 xa = __ldcs((const float2*)(xpg + r0 * 3 * HD + 2 * HD + colb + ej));
            float2 xb = __ldcs((const float2*)(xpg + (r0 + 8) * 3 * HD + 2 * HD + colb + ej));
            float t0 = tanh_f(acc2[0] + xa.x), t1 = tanh_f(acc2[1] + xa.y);
            float t2 = tanh_f(acc2[2] + xb.x), t3 = tanh_f(acc2[3] + xb.y);
            float z00 = zsm[ej * 64 + r0], z01 = zsm[(ej + 1) * 64 + r0];
            float z10 = zsm[ej * 64 + r0 + 8], z11 = zsm[(ej + 1) * 64 + r0 + 8];
            const float* Hc = g_H[p];
            float* Hn = g_H[p ^ 1];
            float h00 = ldcg_f(Hc + (colb + ej) * BB + r0);
            float h01 = ldcg_f(Hc + (colb + ej + 1) * BB + r0);
            float h10 = ldcg_f(Hc + (colb + ej) * BB + r0 + 8);
            float h11 = ldcg_f(Hc + (colb + ej + 1) * BB + r0 + 8);
            float n00 = z00 * h00 + (1.f - z00) * t0;
            float n01 = z01 * h01 + (1.f - z01) * t1;
            float n10 = z10 * h10 + (1.f - z10) * t2;
            float n11 = z11 * h11 + (1.f - z11) * t3;
            Hn[(colb + ej) * BB + r0] = n00;
            Hn[(colb + ej + 1) * BB + r0] = n01;
            Hn[(colb + ej) * BB + r0 + 8] = n10;
            Hn[(colb + ej + 1) * BB + r0 + 8] = n11;
            st_hilo(&g_Hbf[p ^ 1][0][r0][colb + ej], &g_Hbf[p ^ 1][1][r0][colb + ej], n00, n01);
            st_hilo(&g_Hbf[p ^ 1][0][r0 + 8][colb + ej], &g_Hbf[p ^ 1][1][r0 + 8][colb + ej], n10, n11);
        }
        __syncthreads();
        if (tid == 0) { __threadfence(); publish(&g_F2[bx * 32], (unsigned)(s + 1)); }
        p ^= 1;
    }
}

// =====================================================================
// Kernel 3: logits + softmax
// =====================================================================
__global__ __launch_bounds__(256) void out_kernel(const float* __restrict__ Whq,
                                                  const float* __restrict__ bq,
                                                  float* __restrict__ out) {
    const int b = blockIdx.x, t = threadIdx.x;
    float acc[NO];
#pragma unroll
    for (int o = 0; o < NO; o++) acc[o] = 0.f;
#pragma unroll
    for (int i = 0; i < HD / 256; i++) {
        int k = t + i * 256;
        float hv = g_H[0][k * BB + b];
        const float* wp = Whq + (size_t)k * NO;
#pragma unroll
        for (int o = 0; o < NO; o++) acc[o] += hv * wp[o];
    }
    __shared__ float part[256 * NO];
#pragma unroll
    for (int o = 0; o < NO; o++) part[t * NO + o] = acc[o];
    __syncthreads();
    __shared__ float logits[NO];
    if (t < NO) {
        float sum = bq[t];
        for (int i = 0; i < 256; i++) sum += part[i * NO + t];
        logits[t] = sum;
    }
    __syncthreads();
    if (t == 0) {
        float mx = logits[0];
#pragma unroll
        for (int o = 1; o < NO; o++) mx = fmaxf(mx, logits[o]);
        float e[NO]; float sum = 0.f;
#pragma unroll
        for (int o = 0; o < NO; o++) { e[o] = __expf(logits[o] - mx); sum += e[o]; }
        float inv = 1.0f / sum;
#pragma unroll
        for (int o = 0; o < NO; o++) out[b * NO + o] = e[o] * inv;
    }
}

// =====================================================================
extern "C" void kernel_launch(void* const* d_in, const int* in_sizes, int n_in,
                              void* d_out, int out_size) {
    const int*   inputs = (const int*)d_in[0];
    const float* emb = (const float*)d_in[1];
    const float* Wxr = (const float*)d_in[2];
    const float* Whr = (const float*)d_in[3];
    const float* br  = (const float*)d_in[4];
    const float* Wxz = (const float*)d_in[5];
    const float* Whz = (const float*)d_in[6];
    const float* bz  = (const float*)d_in[7];
    const float* Wxc = (const float*)d_in[8];
    const float* Whc = (const float*)d_in[9];
    const float* bc  = (const float*)d_in[10];
    const float* Whq = (const float*)d_in[11];
    const float* bq  = (const float*)d_in[12];
    float* out = (float*)d_out;

    static int smem_set = 0;
    if (!smem_set) {
        cudaFuncSetAttribute(gru_kernel,
                             cudaFuncAttributeMaxDynamicSharedMemorySize, GRU_SMEM);
        smem_set = 1;
    }

    reset_kernel<<<1, 256>>>();
    dim3 wg(512, 3);
    wconv_kernel<<<wg, 256>>>(Wxr, Wxz, Wxc);
    dim3 wrg(1024, 3);
    wrconv_kernel<<<wrg, 256>>>(Whr, Whz, Whc);
    dim3 pg(48, 512);
    proj_kernel<<<pg, 256>>>(inputs, emb, br, bz, bc);
    gru_kernel<<<NBLK, GTHR, GRU_SMEM>>>();
    out_kernel<<<64, 256>>>(Whq, bq, out);
}

// round 16
// speedup vs baseline: 1.2796x; 1.2796x over previous
#include <cuda_runtime.h>
#include <cuda_bf16.h>

#define BB 64
#define SS 512
#define EE 512
#define HD 1024
#define NO 10
#define NBLK 128
#define GTHR 512

typedef unsigned long long ull;
typedef __nv_bfloat16 bf16;

// -------- scratch --------
__device__ float g_xproj[(size_t)SS * BB * 3 * HD];
__device__ float g_H[2][HD * BB];                 // fp32 [k][b]
__device__ bf16  g_Hbf[2][2][BB][HD];             // [parity][hi/lo][b][k]
__device__ bf16  g_Hrbf[2][2][BB][HD];            // [s&1][hi/lo][b][k]
__device__ unsigned g_arrive[NBLK * 32];
__device__ unsigned g_F1[NBLK * 32];
__device__ unsigned g_F2[NBLK * 32];
__device__ bf16 g_wt[3][2][HD][EE];               // proj W [gate][h][n][k]
__device__ bf16 g_wrt[3][2][HD][HD];              // recur W [gate][h][n][k]

// -------- helpers --------
__device__ __forceinline__ float sigmoid_f(float x) { return 1.0f / (1.0f + __expf(-x)); }
__device__ __forceinline__ float tanh_f(float x) {
    float ax = fabsf(x), t = __expf(-2.0f * ax);
    return copysignf(__fdividef(1.0f - t, 1.0f + t), x);
}
__device__ __forceinline__ float ldcg_f(const float* p) {
    float v; asm("ld.global.cg.f32 %0, [%1];" : "=f"(v) : "l"(p)); return v;
}
__device__ __forceinline__ void st_hilo(bf16* hi, bf16* lo, float a, float b) {
    bf16 h0 = __float2bfloat16_rn(a), h1 = __float2bfloat16_rn(b);
    __nv_bfloat162 H; H.x = h0; H.y = h1;
    *(__nv_bfloat162*)hi = H;
    __nv_bfloat162 L;
    L.x = __float2bfloat16_rn(a - __bfloat162float(h0));
    L.y = __float2bfloat16_rn(b - __bfloat162float(h1));
    *(__nv_bfloat162*)lo = L;
}
__device__ __forceinline__ void ldsm_x4(unsigned& r0, unsigned& r1, unsigned& r2,
                                        unsigned& r3, unsigned addr) {
    asm volatile("ldmatrix.sync.aligned.m8n8.x4.shared.b16 {%0,%1,%2,%3}, [%4];"
                 : "=r"(r0), "=r"(r1), "=r"(r2), "=r"(r3) : "r"(addr));
}
__device__ __forceinline__ void ldsm_x2(unsigned& r0, unsigned& r1, unsigned addr) {
    asm volatile("ldmatrix.sync.aligned.m8n8.x2.shared.b16 {%0,%1}, [%2];"
                 : "=r"(r0), "=r"(r1) : "r"(addr));
}
__device__ __forceinline__ void mma_bf16(float* c, const unsigned* a,
                                         unsigned b0, unsigned b1) {
    asm volatile(
        "mma.sync.aligned.m16n8k16.row.col.f32.bf16.bf16.f32 "
        "{%0,%1,%2,%3},{%4,%5,%6,%7},{%8,%9},{%0,%1,%2,%3};"
        : "+f"(c[0]), "+f"(c[1]), "+f"(c[2]), "+f"(c[3])
        : "r"(a[0]), "r"(a[1]), "r"(a[2]), "r"(a[3]), "r"(b0), "r"(b1));
}
__device__ __forceinline__ void publish(unsigned* slot, unsigned val) {
    asm volatile("st.release.gpu.u32 [%0], %1;" :: "l"(slot), "r"(val) : "memory");
}
__device__ __forceinline__ void poll_flag(const unsigned* p, unsigned target) {
    unsigned v;
    for (;;) {
        asm volatile("ld.relaxed.gpu.u32 %0, [%1];" : "=r"(v) : "l"(p) : "memory");
        if (v >= target) break;
        __nanosleep(20);
    }
    asm volatile("ld.acquire.gpu.u32 %0, [%1];" : "=r"(v) : "l"(p) : "memory");
}
__device__ __forceinline__ void flat_barrier(unsigned target, int bx) {
    __syncthreads();
    if (threadIdx.x == 0) {
        __threadfence();
        publish(&g_arrive[bx * 32], target);
    }
    if (threadIdx.x < NBLK) {
        const unsigned* p = &g_arrive[threadIdx.x * 32];
        unsigned v;
        do {
            asm volatile("ld.acquire.gpu.u32 %0, [%1];" : "=r"(v) : "l"(p) : "memory");
        } while (v < target);
    }
    __syncthreads();
}

__global__ void reset_kernel() {
    int t = threadIdx.x;
    for (int i = t; i < NBLK * 32; i += blockDim.x) {
        g_arrive[i] = 0u; g_F1[i] = 0u; g_F2[i] = 0u;
    }
}

// ---- weight converts ----
__global__ __launch_bounds__(256) void wconv_kernel(
    const float* __restrict__ Wxr, const float* __restrict__ Wxz,
    const float* __restrict__ Wxc) {
    const int k = blockIdx.x, gate = blockIdx.y;
    const float* W = (gate == 0) ? Wxr : ((gate == 1) ? Wxz : Wxc);
    const int n0 = threadIdx.x * 4;
    float4 v = *(const float4*)(W + (size_t)k * HD + n0);
    float xs[4] = {v.x, v.y, v.z, v.w};
#pragma unroll
    for (int i = 0; i < 4; i++) {
        bf16 h = __float2bfloat16_rn(xs[i]);
        g_wt[gate][0][n0 + i][k] = h;
        g_wt[gate][1][n0 + i][k] = __float2bfloat16_rn(xs[i] - __bfloat162float(h));
    }
}
__global__ __launch_bounds__(256) void wrconv_kernel(
    const float* __restrict__ Whr, const float* __restrict__ Whz,
    const float* __restrict__ Whc) {
    const int k = blockIdx.x, gate = blockIdx.y;
    const float* W = (gate == 0) ? Whr : ((gate == 1) ? Whz : Whc);
    const int n0 = threadIdx.x * 4;
    float4 v = *(const float4*)(W + (size_t)k * HD + n0);
    float xs[4] = {v.x, v.y, v.z, v.w};
#pragma unroll
    for (int i = 0; i < 4; i++) {
        bf16 h = __float2bfloat16_rn(xs[i]);
        g_wrt[gate][0][n0 + i][k] = h;
        g_wrt[gate][1][n0 + i][k] = __float2bfloat16_rn(xs[i] - __bfloat162float(h));
    }
}

// =====================================================================
// Kernel 1: proj via split-bf16 mma (R13, proven)
// =====================================================================
__global__ __launch_bounds__(256) void proj_kernel(
    const int* __restrict__ inputs, const float* __restrict__ emb,
    const float* __restrict__ br, const float* __restrict__ bz,
    const float* __restrict__ bc) {
    __shared__ __align__(16) bf16 Ahi[64][72], Alo[64][72];
    __shared__ __align__(16) bf16 Bhi[64][72], Blo[64][72];
    __shared__ int tok[64];

    const int s = blockIdx.y, nt = blockIdx.x;
    const int gate = nt >> 4, gc0 = (nt & 15) * 64;
    const float* bias = (gate == 0) ? br : ((gate == 1) ? bz : bc);
    const int tid = threadIdx.x, w = tid >> 5, lane = tid & 31;
    const int m0w = (w & 3) * 16, n0w = (w >> 2) * 32;

    if (tid < 64) tok[tid] = inputs[tid * SS + s];
    __syncthreads();

    const int am = tid >> 2, akq = (tid & 3) * 16;
    const int bh = tid >> 7, bn = (tid & 127) >> 1, bkq = (tid & 1) * 32;
    const float* arow = emb + (size_t)tok[am] * EE + akq;
    const bf16* bsrc = &g_wt[gate][bh][gc0 + bn][0] + bkq;

    unsigned a_hi_base = (unsigned)__cvta_generic_to_shared(
        &Ahi[m0w + (lane & 7) + ((lane >> 3) & 1) * 8][((lane >> 4) & 1) * 8]);
    unsigned a_lo_base = (unsigned)__cvta_generic_to_shared(
        &Alo[m0w + (lane & 7) + ((lane >> 3) & 1) * 8][((lane >> 4) & 1) * 8]);
    const int brow = ((lane >> 4) & 1) * 8 + (lane & 7);
    const int bcol = ((lane >> 3) & 1) * 8;
    unsigned b_hi0 = (unsigned)__cvta_generic_to_shared(&Bhi[n0w + brow][bcol]);
    unsigned b_hi1 = (unsigned)__cvta_generic_to_shared(&Bhi[n0w + 16 + brow][bcol]);
    unsigned b_lo0 = (unsigned)__cvta_generic_to_shared(&Blo[n0w + brow][bcol]);
    unsigned b_lo1 = (unsigned)__cvta_generic_to_shared(&Blo[n0w + 16 + brow][bcol]);

    float acc[4][4];
#pragma unroll
    for (int a = 0; a < 4; a++)
#pragma unroll
        for (int i = 0; i < 4; i++) acc[a][i] = 0.f;

    float a_reg[16];
    uint4 b_reg[4];
    *(float4*)(a_reg + 0)  = *(const float4*)(arow + 0);
    *(float4*)(a_reg + 4)  = *(const float4*)(arow + 4);
    *(float4*)(a_reg + 8)  = *(const float4*)(arow + 8);
    *(float4*)(a_reg + 12) = *(const float4*)(arow + 12);
    b_reg[0] = *(const uint4*)(bsrc);
    b_reg[1] = *(const uint4*)(bsrc + 8);
    b_reg[2] = *(const uint4*)(bsrc + 16);
    b_reg[3] = *(const uint4*)(bsrc + 24);

#pragma unroll 1
    for (int c = 0; c < 8; ++c) {
#pragma unroll
        for (int i = 0; i < 16; i += 2)
            st_hilo(&Ahi[am][akq + i], &Alo[am][akq + i], a_reg[i], a_reg[i + 1]);
        {
            bf16 (*Bd)[72] = bh ? Blo : Bhi;
            *(uint4*)&Bd[bn][bkq]      = b_reg[0];
            *(uint4*)&Bd[bn][bkq + 8]  = b_reg[1];
            *(uint4*)&Bd[bn][bkq + 16] = b_reg[2];
            *(uint4*)&Bd[bn][bkq + 24] = b_reg[3];
        }
        __syncthreads();
        if (c < 7) {
            const float* an = arow + (c + 1) * 64;
            *(float4*)(a_reg + 0)  = *(const float4*)(an + 0);
            *(float4*)(a_reg + 4)  = *(const float4*)(an + 4);
            *(float4*)(a_reg + 8)  = *(const float4*)(an + 8);
            *(float4*)(a_reg + 12) = *(const float4*)(an + 12);
            const bf16* bnp = bsrc + (c + 1) * 64;
            b_reg[0] = *(const uint4*)(bnp);
            b_reg[1] = *(const uint4*)(bnp + 8);
            b_reg[2] = *(const uint4*)(bnp + 16);
            b_reg[3] = *(const uint4*)(bnp + 24);
        }
#pragma unroll
        for (int ks = 0; ks < 4; ++ks) {
            const unsigned off = ks * 32;
            unsigned ah[4], al[4], h0[4], h1[4], l0[4], l1[4];
            ldsm_x4(ah[0], ah[1], ah[2], ah[3], a_hi_base + off);
            ldsm_x4(al[0], al[1], al[2], al[3], a_lo_base + off);
            ldsm_x4(h0[0], h0[1], h0[2], h0[3], b_hi0 + off);
            ldsm_x4(h1[0], h1[1], h1[2], h1[3], b_hi1 + off);
            ldsm_x4(l0[0], l0[1], l0[2], l0[3], b_lo0 + off);
            ldsm_x4(l1[0], l1[1], l1[2], l1[3], b_lo1 + off);
            mma_bf16(acc[0], ah, h0[0], h0[1]);
            mma_bf16(acc[0], ah, l0[0], l0[1]);
            mma_bf16(acc[0], al, h0[0], h0[1]);
            mma_bf16(acc[1], ah, h0[2], h0[3]);
            mma_bf16(acc[1], ah, l0[2], l0[3]);
            mma_bf16(acc[1], al, h0[2], h0[3]);
            mma_bf16(acc[2], ah, h1[0], h1[1]);
            mma_bf16(acc[2], ah, l1[0], l1[1]);
            mma_bf16(acc[2], al, h1[0], h1[1]);
            mma_bf16(acc[3], ah, h1[2], h1[3]);
            mma_bf16(acc[3], ah, l1[2], l1[3]);
            mma_bf16(acc[3], al, h1[2], h1[3]);
        }
        __syncthreads();
    }
    const int row0 = m0w + (lane >> 2);
#pragma unroll
    for (int a = 0; a < 4; a++) {
        const int col = gc0 + n0w + a * 8 + 2 * (lane & 3);
        float2 bi = *(const float2*)(bias + col);
        float2 v0 = make_float2(acc[a][0] + bi.x, acc[a][1] + bi.y);
        float2 v1 = make_float2(acc[a][2] + bi.x, acc[a][3] + bi.y);
        float* base = g_xproj + ((size_t)s * BB + row0) * (3 * HD) + gate * HD + col;
        __stcs((float2*)base, v0);
        __stcs((float2*)(base + 8 * 3 * HD), v1);
    }
}

// =====================================================================
// Kernel 2: MMA GRU, coarse phase waits + double-buffered A staging.
// =====================================================================
#define ASTR 136
#define ABUF (64 * ASTR)
#define BSTR 1032
#define B1_OFF (4 * ABUF)
#define B2_OFF (B1_OFF + 2 * 16 * BSTR)
#define GSM_BF (B2_OFF + 2 * 8 * BSTR)
#define GRU_SMEM (GSM_BF * 2)

__global__ __launch_bounds__(GTHR, 1) void gru_kernel() {
    extern __shared__ __align__(16) bf16 sm[];
    __shared__ float red[12 * 128];
    __shared__ float zsm[8 * 64];

    const int tid = threadIdx.x, bx = blockIdx.x;
    const int w = tid >> 5, lane = tid & 31;
    const int colb = bx * 8;

    for (int i = bx * GTHR + tid; i < HD * BB / 4; i += NBLK * GTHR)
        ((float4*)g_H[0])[i] = make_float4(0.f, 0.f, 0.f, 0.f);
    for (int i = bx * GTHR + tid; i < 2 * BB * HD / 8; i += NBLK * GTHR)
        ((uint4*)g_Hbf[0])[i] = make_uint4(0, 0, 0, 0);
    flat_barrier(1, bx);

    // resident weights
    for (int g = tid; g < 4096; g += GTHR) {
        int h = g >> 11, n = (g >> 7) & 15, kq = (g & 127) * 8;
        *(uint4*)&sm[B1_OFF + (h * 16 + n) * BSTR + kq] =
            *(const uint4*)&g_wrt[n >> 3][h][colb + (n & 7)][kq];
    }
    for (int g = tid; g < 2048; g += GTHR) {
        int h = g >> 10, n = (g >> 7) & 7, kq = (g & 127) * 8;
        *(uint4*)&sm[B2_OFF + (h * 8 + n) * BSTR + kq] =
            *(const uint4*)&g_wrt[2][h][colb + n][kq];
    }
    __syncthreads();

    const int mt = w & 3;
    const int nt1 = (w >> 2) & 1, kh1 = w >> 3;
    const int kq2 = w >> 2;
    unsigned a_hi_b = (unsigned)__cvta_generic_to_shared(
        &sm[(mt * 16 + (lane & 7) + ((lane >> 3) & 1) * 8) * ASTR + ((lane >> 4) & 1) * 8]);
    const unsigned BUFB = (unsigned)(2 * ABUF * 2);   // bytes between A buffers
    const unsigned LOB  = (unsigned)(ABUF * 2);       // hi->lo offset bytes
    const int bl = lane & 15;
    unsigned b1h = (unsigned)__cvta_generic_to_shared(
        &sm[B1_OFF + (nt1 * 8 + (bl & 7)) * BSTR + ((bl >> 3) & 1) * 8]);
    unsigned b1l = b1h + 16 * BSTR * 2;
    unsigned b2h = (unsigned)__cvta_generic_to_shared(
        &sm[B2_OFF + (bl & 7) * BSTR + ((bl >> 3) & 1) * 8]);
    unsigned b2l = b2h + 8 * BSTR * 2;
    const int er = (lane >> 2);
    const int ej = 2 * (lane & 3);
    const int sb = tid >> 3, skq = (tid & 7) * 16;   // staging map

    int p = 0;
#pragma unroll 1
    for (int s = 0; s < SS; ++s) {
        const float* xpg = g_xproj + (size_t)s * BB * 3 * HD;
        const int par = s & 1;

        // ---------- phase 1 ----------
        if (tid < NBLK) poll_flag(&g_F2[tid * 32], (unsigned)s);
        __syncthreads();
        float acc1[4] = {0.f, 0.f, 0.f, 0.f};
        {
            uint4 rh0, rh1, rl0, rl1;
            const bf16* sh = &g_Hbf[p][0][sb][skq];
            const bf16* sl = &g_Hbf[p][1][sb][skq];
            rh0 = *(const uint4*)sh; rh1 = *(const uint4*)(sh + 8);
            rl0 = *(const uint4*)sl; rl1 = *(const uint4*)(sl + 8);
            bf16* dh = &sm[sb * ASTR + skq];
            *(uint4*)dh = rh0; *(uint4*)(dh + 8) = rh1;
            *(uint4*)(dh + ABUF) = rl0; *(uint4*)(dh + ABUF + 8) = rl1;
            __syncthreads();
#pragma unroll 1
            for (int c = 0; c < 8; ++c) {
                if (c < 7) {
                    const bf16* nh = &g_Hbf[p][0][sb][(c + 1) * 128 + skq];
                    const bf16* nl = &g_Hbf[p][1][sb][(c + 1) * 128 + skq];
                    rh0 = *(const uint4*)nh; rh1 = *(const uint4*)(nh + 8);
                    rl0 = *(const uint4*)nl; rl1 = *(const uint4*)(nl + 8);
                }
                const unsigned bufo = (unsigned)(c & 1) * BUFB;
#pragma unroll
                for (int ks = 0; ks < 4; ++ks) {
                    unsigned aoff = bufo + (kh1 * 64 + ks * 16) * 2;
                    unsigned boff = (c * 128 + kh1 * 64 + ks * 16) * 2;
                    unsigned ah[4], al[4], bh0, bh1, bl0, bl1;
                    ldsm_x4(ah[0], ah[1], ah[2], ah[3], a_hi_b + aoff);
                    ldsm_x4(al[0], al[1], al[2], al[3], a_hi_b + aoff + LOB);
                    ldsm_x2(bh0, bh1, b1h + boff);
                    ldsm_x2(bl0, bl1, b1l + boff);
                    mma_bf16(acc1, ah, bh0, bh1);
                    mma_bf16(acc1, ah, bl0, bl1);
                    mma_bf16(acc1, al, bh0, bh1);
                }
                if (c < 7) {
                    bf16* dn = &sm[((c + 1) & 1) * 2 * ABUF + sb * ASTR + skq];
                    *(uint4*)dn = rh0; *(uint4*)(dn + 8) = rh1;
                    *(uint4*)(dn + ABUF) = rl0; *(uint4*)(dn + ABUF + 8) = rl1;
                    __syncthreads();
                }
            }
        }
        if (w >= 8) *(float4*)&red[((w - 8) * 32 + lane) * 4] = *(float4*)acc1;
        __syncthreads();
        if (w < 8) {
            float4 o = *(float4*)&red[(w * 32 + lane) * 4];
            acc1[0] += o.x; acc1[1] += o.y; acc1[2] += o.z; acc1[3] += o.w;
            const int r0 = mt * 16 + er;
            float2 xa = __ldcs((const float2*)(xpg + r0 * 3 * HD + nt1 * HD + colb + ej));
            float2 xb = __ldcs((const float2*)(xpg + (r0 + 8) * 3 * HD + nt1 * HD + colb + ej));
            float v0 = sigmoid_f(acc1[0] + xa.x), v1 = sigmoid_f(acc1[1] + xa.y);
            float v2 = sigmoid_f(acc1[2] + xb.x), v3 = sigmoid_f(acc1[3] + xb.y);
            if (nt1 == 0) {
                const float* Hc = g_H[p];
                float h00 = ldcg_f(Hc + (colb + ej) * BB + r0);
                float h01 = ldcg_f(Hc + (colb + ej + 1) * BB + r0);
                float h10 = ldcg_f(Hc + (colb + ej) * BB + r0 + 8);
                float h11 = ldcg_f(Hc + (colb + ej + 1) * BB + r0 + 8);
                st_hilo(&g_Hrbf[par][0][r0][colb + ej], &g_Hrbf[par][1][r0][colb + ej],
                        h00 * v0, h01 * v1);
                st_hilo(&g_Hrbf[par][0][r0 + 8][colb + ej], &g_Hrbf[par][1][r0 + 8][colb + ej],
                        h10 * v2, h11 * v3);
            } else {
                zsm[ej * 64 + r0] = v0; zsm[(ej + 1) * 64 + r0] = v1;
                zsm[ej * 64 + r0 + 8] = v2; zsm[(ej + 1) * 64 + r0 + 8] = v3;
            }
        }
        __syncthreads();
        if (tid == 0) { __threadfence(); publish(&g_F1[bx * 32], (unsigned)(s + 1)); }

        // ---------- phase 2 ----------
        if (tid < NBLK) poll_flag(&g_F1[tid * 32], (unsigned)(s + 1));
        __syncthreads();
        float acc2[4] = {0.f, 0.f, 0.f, 0.f};
        {
            uint4 rh0, rh1, rl0, rl1;
            const bf16* sh = &g_Hrbf[par][0][sb][skq];
            const bf16* sl = &g_Hrbf[par][1][sb][skq];
            rh0 = *(const uint4*)sh; rh1 = *(const uint4*)(sh + 8);
            rl0 = *(const uint4*)sl; rl1 = *(const uint4*)(sl + 8);
            bf16* dh = &sm[sb * ASTR + skq];
            *(uint4*)dh = rh0; *(uint4*)(dh + 8) = rh1;
            *(uint4*)(dh + ABUF) = rl0; *(uint4*)(dh + ABUF + 8) = rl1;
            __syncthreads();
#pragma unroll 1
            for (int c = 0; c < 8; ++c) {
                if (c < 7) {
                    const bf16* nh = &g_Hrbf[par][0][sb][(c + 1) * 128 + skq];
                    const bf16* nl = &g_Hrbf[par][1][sb][(c + 1) * 128 + skq];
                    rh0 = *(const uint4*)nh; rh1 = *(const uint4*)(nh + 8);
                    rl0 = *(const uint4*)nl; rl1 = *(const uint4*)(nl + 8);
                }
                const unsigned bufo = (unsigned)(c & 1) * BUFB;
#pragma unroll
                for (int ks = 0; ks < 2; ++ks) {
                    unsigned aoff = bufo + (kq2 * 32 + ks * 16) * 2;
                    unsigned boff = (c * 128 + kq2 * 32 + ks * 16) * 2;
                    unsigned ah[4], al[4], bh0, bh1, bl0, bl1;
                    ldsm_x4(ah[0], ah[1], ah[2], ah[3], a_hi_b + aoff);
                    ldsm_x4(al[0], al[1], al[2], al[3], a_hi_b + aoff + LOB);
                    ldsm_x2(bh0, bh1, b2h + boff);
                    ldsm_x2(bl0, bl1, b2l + boff);
                    mma_bf16(acc2, ah, bh0, bh1);
                    mma_bf16(acc2, ah, bl0, bl1);
                    mma_bf16(acc2, al, bh0, bh1);
                }
                if (c < 7) {
                    bf16* dn = &sm[((c + 1) & 1) * 2 * ABUF + sb * ASTR + skq];
                    *(uint4*)dn = rh0; *(uint4*)(dn + 8) = rh1;
                    *(uint4*)(dn + ABUF) = rl0; *(uint4*)(dn + ABUF + 8) = rl1;
                    __syncthreads();
                }
            }
        }
        if (w >= 4) *(float4*)&red[((w - 4) * 32 + lane) * 4] = *(float4*)acc2;
        __syncthreads();
        if (w < 4) {
#pragma unroll
            for (int q = 0; q < 3; ++q) {
                float4 o = *(float4*)&red[((q * 4 + w) * 32 + lane) * 4];
                acc2[0] += o.x; acc2[1] += o.y; acc2[2] += o.z; acc2[3] += o.w;
            }
            const int r0 = mt * 16 + er;
            float2 xa = __ldcs((const float2*)(xpg + r0 * 3 * HD + 2 * HD + colb + ej));
            float2 xb = __ldcs((const float2*)(xpg + (r0 + 8) * 3 * HD + 2 * HD + colb + ej));
            float t0 = tanh_f(acc2[0] + xa.x), t1 = tanh_f(acc2[1] + xa.y);
            float t2 = tanh_f(acc2[2] + xb.x), t3 = tanh_f(acc2[3] + xb.y);
            float z00 = zsm[ej * 64 + r0], z01 = zsm[(ej + 1) * 64 + r0];
            float z10 = zsm[ej * 64 + r0 + 8], z11 = zsm[(ej + 1) * 64 + r0 + 8];
            const float* Hc = g_H[p];
            float* Hn = g_H[p ^ 1];
            float h00 = ldcg_f(Hc + (colb + ej) * BB + r0);
            float h01 = ldcg_f(Hc + (colb + ej + 1) * BB + r0);
            float h10 = ldcg_f(Hc + (colb + ej) * BB + r0 + 8);
            float h11 = ldcg_f(Hc + (colb + ej + 1) * BB + r0 + 8);
            float n00 = z00 * h00 + (1.f - z00) * t0;
            float n01 = z01 * h01 + (1.f - z01) * t1;
            float n10 = z10 * h10 + (1.f - z10) * t2;
            float n11 = z11 * h11 + (1.f - z11) * t3;
            Hn[(colb + ej) * BB + r0] = n00;
            Hn[(colb + ej + 1) * BB + r0] = n01;
            Hn[(colb + ej) * BB + r0 + 8] = n10;
            Hn[(colb + ej + 1) * BB + r0 + 8] = n11;
            st_hilo(&g_Hbf[p ^ 1][0][r0][colb + ej], &g_Hbf[p ^ 1][1][r0][colb + ej], n00, n01);
            st_hilo(&g_Hbf[p ^ 1][0][r0 + 8][colb + ej], &g_Hbf[p ^ 1][1][r0 + 8][colb + ej], n10, n11);
        }
        __syncthreads();
        if (tid == 0) { __threadfence(); publish(&g_F2[bx * 32], (unsigned)(s + 1)); }
        p ^= 1;
    }
}

// =====================================================================
// Kernel 3: logits + softmax
// =====================================================================
__global__ __launch_bounds__(256) void out_kernel(const float* __restrict__ Whq,
                                                  const float* __restrict__ bq,
                                                  float* __restrict__ out) {
    const int b = blockIdx.x, t = threadIdx.x;
    float acc[NO];
#pragma unroll
    for (int o = 0; o < NO; o++) acc[o] = 0.f;
#pragma unroll
    for (int i = 0; i < HD / 256; i++) {
        int k = t + i * 256;
        float hv = g_H[0][k * BB + b];
        const float* wp = Whq + (size_t)k * NO;
#pragma unroll
        for (int o = 0; o < NO; o++) acc[o] += hv * wp[o];
    }
    __shared__ float part[256 * NO];
#pragma unroll
    for (int o = 0; o < NO; o++) part[t * NO + o] = acc[o];
    __syncthreads();
    __shared__ float logits[NO];
    if (t < NO) {
        float sum = bq[t];
        for (int i = 0; i < 256; i++) sum += part[i * NO + t];
        logits[t] = sum;
    }
    __syncthreads();
    if (t == 0) {
        float mx = logits[0];
#pragma unroll
        for (int o = 1; o < NO; o++) mx = fmaxf(mx, logits[o]);
        float e[NO]; float sum = 0.f;
#pragma unroll
        for (int o = 0; o < NO; o++) { e[o] = __expf(logits[o] - mx); sum += e[o]; }
        float inv = 1.0f / sum;
#pragma unroll
        for (int o = 0; o < NO; o++) out[b * NO + o] = e[o] * inv;
    }
}

// =====================================================================
extern "C" void kernel_launch(void* const* d_in, const int* in_sizes, int n_in,
                              void* d_out, int out_size) {
    const int*   inputs = (const int*)d_in[0];
    const float* emb = (const float*)d_in[1];
    const float* Wxr = (const float*)d_in[2];
    const float* Whr = (const float*)d_in[3];
    const float* br  = (const float*)d_in[4];
    const float* Wxz = (const float*)d_in[5];
    const float* Whz = (const float*)d_in[6];
    const float* bz  = (const float*)d_in[7];
    const float* Wxc = (const float*)d_in[8];
    const float* Whc = (const float*)d_in[9];
    const float* bc  = (const float*)d_in[10];
    const float* Whq = (const float*)d_in[11];
    const float* bq  = (const float*)d_in[12];
    float* out = (float*)d_out;

    static int smem_set = 0;
    if (!smem_set) {
        cudaFuncSetAttribute(gru_kernel,
                             cudaFuncAttributeMaxDynamicSharedMemorySize, GRU_SMEM);
        smem_set = 1;
    }

    reset_kernel<<<1, 256>>>();
    dim3 wg(512, 3);
    wconv_kernel<<<wg, 256>>>(Wxr, Wxz, Wxc);
    dim3 wrg(1024, 3);
    wrconv_kernel<<<wrg, 256>>>(Whr, Whz, Whc);
    dim3 pg(48, 512);
    proj_kernel<<<pg, 256>>>(inputs, emb, br, bz, bc);
    gru_kernel<<<NBLK, GTHR, GRU_SMEM>>>();
    out_kernel<<<64, 256>>>(Whq, bq, out);
}

// round 17
// speedup vs baseline: 1.3438x; 1.0501x over previous
#include <cuda_runtime.h>
#include <cuda_bf16.h>

#define BB 64
#define SS 512
#define EE 512
#define HD 1024
#define NO 10
#define NBLK 128
#define GTHR 512

typedef unsigned long long ull;
typedef __nv_bfloat16 bf16;

// -------- scratch --------
__device__ float g_xproj[(size_t)SS * BB * 3 * HD];
__device__ float g_H[2][HD * BB];                 // fp32 [k][b]
__device__ bf16  g_Hbf[2][2][BB][HD];             // [parity][hi/lo][b][k]
__device__ bf16  g_Hrbf[2][2][BB][HD];            // [s&1][hi/lo][b][k]
__device__ unsigned g_arrive[NBLK * 32];
__device__ unsigned g_F1[NBLK * 32];
__device__ unsigned g_F2[NBLK * 32];
__device__ bf16 g_wt[3][2][HD][EE];               // proj W [gate][h][n][k]
__device__ bf16 g_wrt[3][2][HD][HD];              // recur W [gate][h][n][k]

// -------- helpers --------
__device__ __forceinline__ float sigmoid_f(float x) { return 1.0f / (1.0f + __expf(-x)); }
__device__ __forceinline__ float tanh_f(float x) {
    float ax = fabsf(x), t = __expf(-2.0f * ax);
    return copysignf(__fdividef(1.0f - t, 1.0f + t), x);
}
__device__ __forceinline__ float ldcg_f(const float* p) {
    float v; asm("ld.global.cg.f32 %0, [%1];" : "=f"(v) : "l"(p)); return v;
}
__device__ __forceinline__ void st_hilo(bf16* hi, bf16* lo, float a, float b) {
    bf16 h0 = __float2bfloat16_rn(a), h1 = __float2bfloat16_rn(b);
    __nv_bfloat162 H; H.x = h0; H.y = h1;
    *(__nv_bfloat162*)hi = H;
    __nv_bfloat162 L;
    L.x = __float2bfloat16_rn(a - __bfloat162float(h0));
    L.y = __float2bfloat16_rn(b - __bfloat162float(h1));
    *(__nv_bfloat162*)lo = L;
}
__device__ __forceinline__ void ldsm_x4(unsigned& r0, unsigned& r1, unsigned& r2,
                                        unsigned& r3, unsigned addr) {
    asm volatile("ldmatrix.sync.aligned.m8n8.x4.shared.b16 {%0,%1,%2,%3}, [%4];"
                 : "=r"(r0), "=r"(r1), "=r"(r2), "=r"(r3) : "r"(addr));
}
__device__ __forceinline__ void mma_bf16(float* c, const unsigned* a,
                                         unsigned b0, unsigned b1) {
    asm volatile(
        "mma.sync.aligned.m16n8k16.row.col.f32.bf16.bf16.f32 "
        "{%0,%1,%2,%3},{%4,%5,%6,%7},{%8,%9},{%0,%1,%2,%3};"
        : "+f"(c[0]), "+f"(c[1]), "+f"(c[2]), "+f"(c[3])
        : "r"(a[0]), "r"(a[1]), "r"(a[2]), "r"(a[3]), "r"(b0), "r"(b1));
}
__device__ __forceinline__ void publish(unsigned* slot, unsigned val) {
    asm volatile("st.release.gpu.u32 [%0], %1;" :: "l"(slot), "r"(val) : "memory");
}
__device__ __forceinline__ void poll_flag(const unsigned* p, unsigned target) {
    unsigned v;
    for (;;) {
        asm volatile("ld.relaxed.gpu.u32 %0, [%1];" : "=r"(v) : "l"(p) : "memory");
        if (v >= target) break;
        __nanosleep(20);
    }
    asm volatile("ld.acquire.gpu.u32 %0, [%1];" : "=r"(v) : "l"(p) : "memory");
}
__device__ __forceinline__ void flat_barrier(unsigned target, int bx) {
    __syncthreads();
    if (threadIdx.x == 0) {
        __threadfence();
        publish(&g_arrive[bx * 32], target);
    }
    if (threadIdx.x < NBLK) {
        const unsigned* p = &g_arrive[threadIdx.x * 32];
        unsigned v;
        do {
            asm volatile("ld.acquire.gpu.u32 %0, [%1];" : "=r"(v) : "l"(p) : "memory");
        } while (v < target);
    }
    __syncthreads();
}

__global__ void reset_kernel() {
    int t = threadIdx.x;
    for (int i = t; i < NBLK * 32; i += blockDim.x) {
        g_arrive[i] = 0u; g_F1[i] = 0u; g_F2[i] = 0u;
    }
}

// ---- weight converts ----
__global__ __launch_bounds__(256) void wconv_kernel(
    const float* __restrict__ Wxr, const float* __restrict__ Wxz,
    const float* __restrict__ Wxc) {
    const int k = blockIdx.x, gate = blockIdx.y;
    const float* W = (gate == 0) ? Wxr : ((gate == 1) ? Wxz : Wxc);
    const int n0 = threadIdx.x * 4;
    float4 v = *(const float4*)(W + (size_t)k * HD + n0);
    float xs[4] = {v.x, v.y, v.z, v.w};
#pragma unroll
    for (int i = 0; i < 4; i++) {
        bf16 h = __float2bfloat16_rn(xs[i]);
        g_wt[gate][0][n0 + i][k] = h;
        g_wt[gate][1][n0 + i][k] = __float2bfloat16_rn(xs[i] - __bfloat162float(h));
    }
}
__global__ __launch_bounds__(256) void wrconv_kernel(
    const float* __restrict__ Whr, const float* __restrict__ Whz,
    const float* __restrict__ Whc) {
    const int k = blockIdx.x, gate = blockIdx.y;
    const float* W = (gate == 0) ? Whr : ((gate == 1) ? Whz : Whc);
    const int n0 = threadIdx.x * 4;
    float4 v = *(const float4*)(W + (size_t)k * HD + n0);
    float xs[4] = {v.x, v.y, v.z, v.w};
#pragma unroll
    for (int i = 0; i < 4; i++) {
        bf16 h = __float2bfloat16_rn(xs[i]);
        g_wrt[gate][0][n0 + i][k] = h;
        g_wrt[gate][1][n0 + i][k] = __float2bfloat16_rn(xs[i] - __bfloat162float(h));
    }
}

// =====================================================================
// Kernel 1: proj via split-bf16 mma (R13, proven, unchanged)
// =====================================================================
__global__ __launch_bounds__(256) void proj_kernel(
    const int* __restrict__ inputs, const float* __restrict__ emb,
    const float* __restrict__ br, const float* __restrict__ bz,
    const float* __restrict__ bc) {
    __shared__ __align__(16) bf16 Ahi[64][72], Alo[64][72];
    __shared__ __align__(16) bf16 Bhi[64][72], Blo[64][72];
    __shared__ int tok[64];

    const int s = blockIdx.y, nt = blockIdx.x;
    const int gate = nt >> 4, gc0 = (nt & 15) * 64;
    const float* bias = (gate == 0) ? br : ((gate == 1) ? bz : bc);
    const int tid = threadIdx.x, w = tid >> 5, lane = tid & 31;
    const int m0w = (w & 3) * 16, n0w = (w >> 2) * 32;

    if (tid < 64) tok[tid] = inputs[tid * SS + s];
    __syncthreads();

    const int am = tid >> 2, akq = (tid & 3) * 16;
    const int bh = tid >> 7, bn = (tid & 127) >> 1, bkq = (tid & 1) * 32;
    const float* arow = emb + (size_t)tok[am] * EE + akq;
    const bf16* bsrc = &g_wt[gate][bh][gc0 + bn][0] + bkq;

    unsigned a_hi_base = (unsigned)__cvta_generic_to_shared(
        &Ahi[m0w + (lane & 7) + ((lane >> 3) & 1) * 8][((lane >> 4) & 1) * 8]);
    unsigned a_lo_base = (unsigned)__cvta_generic_to_shared(
        &Alo[m0w + (lane & 7) + ((lane >> 3) & 1) * 8][((lane >> 4) & 1) * 8]);
    const int brow = ((lane >> 4) & 1) * 8 + (lane & 7);
    const int bcol = ((lane >> 3) & 1) * 8;
    unsigned b_hi0 = (unsigned)__cvta_generic_to_shared(&Bhi[n0w + brow][bcol]);
    unsigned b_hi1 = (unsigned)__cvta_generic_to_shared(&Bhi[n0w + 16 + brow][bcol]);
    unsigned b_lo0 = (unsigned)__cvta_generic_to_shared(&Blo[n0w + brow][bcol]);
    unsigned b_lo1 = (unsigned)__cvta_generic_to_shared(&Blo[n0w + 16 + brow][bcol]);

    float acc[4][4];
#pragma unroll
    for (int a = 0; a < 4; a++)
#pragma unroll
        for (int i = 0; i < 4; i++) acc[a][i] = 0.f;

    float a_reg[16];
    uint4 b_reg[4];
    *(float4*)(a_reg + 0)  = *(const float4*)(arow + 0);
    *(float4*)(a_reg + 4)  = *(const float4*)(arow + 4);
    *(float4*)(a_reg + 8)  = *(const float4*)(arow + 8);
    *(float4*)(a_reg + 12) = *(const float4*)(arow + 12);
    b_reg[0] = *(const uint4*)(bsrc);
    b_reg[1] = *(const uint4*)(bsrc + 8);
    b_reg[2] = *(const uint4*)(bsrc + 16);
    b_reg[3] = *(const uint4*)(bsrc + 24);

#pragma unroll 1
    for (int c = 0; c < 8; ++c) {
#pragma unroll
        for (int i = 0; i < 16; i += 2)
            st_hilo(&Ahi[am][akq + i], &Alo[am][akq + i], a_reg[i], a_reg[i + 1]);
        {
            bf16 (*Bd)[72] = bh ? Blo : Bhi;
            *(uint4*)&Bd[bn][bkq]      = b_reg[0];
            *(uint4*)&Bd[bn][bkq + 8]  = b_reg[1];
            *(uint4*)&Bd[bn][bkq + 16] = b_reg[2];
            *(uint4*)&Bd[bn][bkq + 24] = b_reg[3];
        }
        __syncthreads();
        if (c < 7) {
            const float* an = arow + (c + 1) * 64;
            *(float4*)(a_reg + 0)  = *(const float4*)(an + 0);
            *(float4*)(a_reg + 4)  = *(const float4*)(an + 4);
            *(float4*)(a_reg + 8)  = *(const float4*)(an + 8);
            *(float4*)(a_reg + 12) = *(const float4*)(an + 12);
            const bf16* bnp = bsrc + (c + 1) * 64;
            b_reg[0] = *(const uint4*)(bnp);
            b_reg[1] = *(const uint4*)(bnp + 8);
            b_reg[2] = *(const uint4*)(bnp + 16);
            b_reg[3] = *(const uint4*)(bnp + 24);
        }
#pragma unroll
        for (int ks = 0; ks < 4; ++ks) {
            const unsigned off = ks * 32;
            unsigned ah[4], al[4], h0[4], h1[4], l0[4], l1[4];
            ldsm_x4(ah[0], ah[1], ah[2], ah[3], a_hi_base + off);
            ldsm_x4(al[0], al[1], al[2], al[3], a_lo_base + off);
            ldsm_x4(h0[0], h0[1], h0[2], h0[3], b_hi0 + off);
            ldsm_x4(h1[0], h1[1], h1[2], h1[3], b_hi1 + off);
            ldsm_x4(l0[0], l0[1], l0[2], l0[3], b_lo0 + off);
            ldsm_x4(l1[0], l1[1], l1[2], l1[3], b_lo1 + off);
            mma_bf16(acc[0], ah, h0[0], h0[1]);
            mma_bf16(acc[0], ah, l0[0], l0[1]);
            mma_bf16(acc[0], al, h0[0], h0[1]);
            mma_bf16(acc[1], ah, h0[2], h0[3]);
            mma_bf16(acc[1], ah, l0[2], l0[3]);
            mma_bf16(acc[1], al, h0[2], h0[3]);
            mma_bf16(acc[2], ah, h1[0], h1[1]);
            mma_bf16(acc[2], ah, l1[0], l1[1]);
            mma_bf16(acc[2], al, h1[0], h1[1]);
            mma_bf16(acc[3], ah, h1[2], h1[3]);
            mma_bf16(acc[3], ah, l1[2], l1[3]);
            mma_bf16(acc[3], al, h1[2], h1[3]);
        }
        __syncthreads();
    }
    const int row0 = m0w + (lane >> 2);
#pragma unroll
    for (int a = 0; a < 4; a++) {
        const int col = gc0 + n0w + a * 8 + 2 * (lane & 3);
        float2 bi = *(const float2*)(bias + col);
        float2 v0 = make_float2(acc[a][0] + bi.x, acc[a][1] + bi.y);
        float2 v1 = make_float2(acc[a][2] + bi.x, acc[a][3] + bi.y);
        float* base = g_xproj + ((size_t)s * BB + row0) * (3 * HD) + gate * HD + col;
        __stcs((float2*)base, v0);
        __stcs((float2*)(base + 8 * 3 * HD), v1);
    }
}

// =====================================================================
// Kernel 2: MMA GRU (R16 schedule) + x4 B-fragments + epilogue prefetch
// =====================================================================
#define ASTR 136
#define ABUF (64 * ASTR)
#define BSTR 1032
#define B1_OFF (4 * ABUF)
#define B2_OFF (B1_OFF + 2 * 16 * BSTR)
#define GSM_BF (B2_OFF + 2 * 8 * BSTR)
#define GRU_SMEM (GSM_BF * 2)

__global__ __launch_bounds__(GTHR, 1) void gru_kernel() {
    extern __shared__ __align__(16) bf16 sm[];
    __shared__ float red[12 * 128];
    __shared__ float zsm[8 * 64];

    const int tid = threadIdx.x, bx = blockIdx.x;
    const int w = tid >> 5, lane = tid & 31;
    const int colb = bx * 8;

    for (int i = bx * GTHR + tid; i < HD * BB / 4; i += NBLK * GTHR)
        ((float4*)g_H[0])[i] = make_float4(0.f, 0.f, 0.f, 0.f);
    for (int i = bx * GTHR + tid; i < 2 * BB * HD / 8; i += NBLK * GTHR)
        ((uint4*)g_Hbf[0])[i] = make_uint4(0, 0, 0, 0);
    flat_barrier(1, bx);

    // resident weights
    for (int g = tid; g < 4096; g += GTHR) {
        int h = g >> 11, n = (g >> 7) & 15, kq = (g & 127) * 8;
        *(uint4*)&sm[B1_OFF + (h * 16 + n) * BSTR + kq] =
            *(const uint4*)&g_wrt[n >> 3][h][colb + (n & 7)][kq];
    }
    for (int g = tid; g < 2048; g += GTHR) {
        int h = g >> 10, n = (g >> 7) & 7, kq = (g & 127) * 8;
        *(uint4*)&sm[B2_OFF + (h * 8 + n) * BSTR + kq] =
            *(const uint4*)&g_wrt[2][h][colb + n][kq];
    }
    __syncthreads();

    const int mt = w & 3;
    const int nt1 = (w >> 2) & 1, kh1 = w >> 3;
    const int kq2 = w >> 2;
    unsigned a_hi_b = (unsigned)__cvta_generic_to_shared(
        &sm[(mt * 16 + (lane & 7) + ((lane >> 3) & 1) * 8) * ASTR + ((lane >> 4) & 1) * 8]);
    const unsigned BUFB = (unsigned)(2 * ABUF * 2);
    const unsigned LOB  = (unsigned)(ABUF * 2);
    // x4 B-fragment addressing: lane -> (n = lane&7, k-group = lane>>3)
    unsigned b1h = (unsigned)__cvta_generic_to_shared(
        &sm[B1_OFF + (nt1 * 8 + (lane & 7)) * BSTR + (lane >> 3) * 8]);
    unsigned b1l = b1h + 16 * BSTR * 2;
    unsigned b2h = (unsigned)__cvta_generic_to_shared(
        &sm[B2_OFF + (lane & 7) * BSTR + (lane >> 3) * 8]);
    unsigned b2l = b2h + 8 * BSTR * 2;
    const int er = (lane >> 2);
    const int ej = 2 * (lane & 3);
    const int sb = tid >> 3, skq = (tid & 7) * 16;

    int p = 0;
#pragma unroll 1
    for (int s = 0; s < SS; ++s) {
        const float* xpg = g_xproj + (size_t)s * BB * 3 * HD;
        const int par = s & 1;
        const int r0 = mt * 16 + er;

        // ---- prefetch epilogue operands (independent of other blocks) ----
        float2 xa1, xb1, xa2, xb2;
        float h1c[4], h2c[4];
        const float* Hc0 = g_H[p];
        if (w < 8) {
            xa1 = __ldcs((const float2*)(xpg + r0 * 3 * HD + nt1 * HD + colb + ej));
            xb1 = __ldcs((const float2*)(xpg + (r0 + 8) * 3 * HD + nt1 * HD + colb + ej));
            if (nt1 == 0) {
                h1c[0] = ldcg_f(Hc0 + (colb + ej) * BB + r0);
                h1c[1] = ldcg_f(Hc0 + (colb + ej + 1) * BB + r0);
                h1c[2] = ldcg_f(Hc0 + (colb + ej) * BB + r0 + 8);
                h1c[3] = ldcg_f(Hc0 + (colb + ej + 1) * BB + r0 + 8);
            }
        }
        if (w < 4) {
            xa2 = __ldcs((const float2*)(xpg + r0 * 3 * HD + 2 * HD + colb + ej));
            xb2 = __ldcs((const float2*)(xpg + (r0 + 8) * 3 * HD + 2 * HD + colb + ej));
            h2c[0] = ldcg_f(Hc0 + (colb + ej) * BB + r0);
            h2c[1] = ldcg_f(Hc0 + (colb + ej + 1) * BB + r0);
            h2c[2] = ldcg_f(Hc0 + (colb + ej) * BB + r0 + 8);
            h2c[3] = ldcg_f(Hc0 + (colb + ej + 1) * BB + r0 + 8);
        }

        // ---------- phase 1 ----------
        if (tid < NBLK) poll_flag(&g_F2[tid * 32], (unsigned)s);
        __syncthreads();
        float acc1[4] = {0.f, 0.f, 0.f, 0.f};
        {
            uint4 rh0, rh1, rl0, rl1;
            const bf16* sh = &g_Hbf[p][0][sb][skq];
            const bf16* sl = &g_Hbf[p][1][sb][skq];
            rh0 = *(const uint4*)sh; rh1 = *(const uint4*)(sh + 8);
            rl0 = *(const uint4*)sl; rl1 = *(const uint4*)(sl + 8);
            bf16* dh = &sm[sb * ASTR + skq];
            *(uint4*)dh = rh0; *(uint4*)(dh + 8) = rh1;
            *(uint4*)(dh + ABUF) = rl0; *(uint4*)(dh + ABUF + 8) = rl1;
            __syncthreads();
#pragma unroll 1
            for (int c = 0; c < 8; ++c) {
                if (c < 7) {
                    const bf16* nh = &g_Hbf[p][0][sb][(c + 1) * 128 + skq];
                    const bf16* nl = &g_Hbf[p][1][sb][(c + 1) * 128 + skq];
                    rh0 = *(const uint4*)nh; rh1 = *(const uint4*)(nh + 8);
                    rl0 = *(const uint4*)nl; rl1 = *(const uint4*)(nl + 8);
                }
                const unsigned bufo = (unsigned)(c & 1) * BUFB;
#pragma unroll
                for (int kp = 0; kp < 2; ++kp) {
                    unsigned boff = (c * 128 + kh1 * 64 + kp * 32) * 2;
                    unsigned bh[4], bl[4];
                    ldsm_x4(bh[0], bh[1], bh[2], bh[3], b1h + boff);
                    ldsm_x4(bl[0], bl[1], bl[2], bl[3], b1l + boff);
#pragma unroll
                    for (int ks = 0; ks < 2; ++ks) {
                        unsigned aoff = bufo + (kh1 * 64 + kp * 32 + ks * 16) * 2;
                        unsigned ah[4], al[4];
                        ldsm_x4(ah[0], ah[1], ah[2], ah[3], a_hi_b + aoff);
                        ldsm_x4(al[0], al[1], al[2], al[3], a_hi_b + aoff + LOB);
                        mma_bf16(acc1, ah, bh[2 * ks], bh[2 * ks + 1]);
                        mma_bf16(acc1, ah, bl[2 * ks], bl[2 * ks + 1]);
                        mma_bf16(acc1, al, bh[2 * ks], bh[2 * ks + 1]);
                    }
                }
                if (c < 7) {
                    bf16* dn = &sm[((c + 1) & 1) * 2 * ABUF + sb * ASTR + skq];
                    *(uint4*)dn = rh0; *(uint4*)(dn + 8) = rh1;
                    *(uint4*)(dn + ABUF) = rl0; *(uint4*)(dn + ABUF + 8) = rl1;
                    __syncthreads();
                }
            }
        }
        if (w >= 8) *(float4*)&red[((w - 8) * 32 + lane) * 4] = *(float4*)acc1;
        __syncthreads();
        if (w < 8) {
            float4 o = *(float4*)&red[(w * 32 + lane) * 4];
            acc1[0] += o.x; acc1[1] += o.y; acc1[2] += o.z; acc1[3] += o.w;
            float v0 = sigmoid_f(acc1[0] + xa1.x), v1 = sigmoid_f(acc1[1] + xa1.y);
            float v2 = sigmoid_f(acc1[2] + xb1.x), v3 = sigmoid_f(acc1[3] + xb1.y);
            if (nt1 == 0) {
                st_hilo(&g_Hrbf[par][0][r0][colb + ej], &g_Hrbf[par][1][r0][colb + ej],
                        h1c[0] * v0, h1c[1] * v1);
                st_hilo(&g_Hrbf[par][0][r0 + 8][colb + ej], &g_Hrbf[par][1][r0 + 8][colb + ej],
                        h1c[2] * v2, h1c[3] * v3);
            } else {
                zsm[ej * 64 + r0] = v0; zsm[(ej + 1) * 64 + r0] = v1;
                zsm[ej * 64 + r0 + 8] = v2; zsm[(ej + 1) * 64 + r0 + 8] = v3;
            }
        }
        __syncthreads();
        if (tid == 0) { __threadfence(); publish(&g_F1[bx * 32], (unsigned)(s + 1)); }

        // ---------- phase 2 ----------
        if (tid < NBLK) poll_flag(&g_F1[tid * 32], (unsigned)(s + 1));
        __syncthreads();
        float acc2[4] = {0.f, 0.f, 0.f, 0.f};
        {
            uint4 rh0, rh1, rl0, rl1;
            const bf16* sh = &g_Hrbf[par][0][sb][skq];
            const bf16* sl = &g_Hrbf[par][1][sb][skq];
            rh0 = *(const uint4*)sh; rh1 = *(const uint4*)(sh + 8);
            rl0 = *(const uint4*)sl; rl1 = *(const uint4*)(sl + 8);
            bf16* dh = &sm[sb * ASTR + skq];
            *(uint4*)dh = rh0; *(uint4*)(dh + 8) = rh1;
            *(uint4*)(dh + ABUF) = rl0; *(uint4*)(dh + ABUF + 8) = rl1;
            __syncthreads();
#pragma unroll 1
            for (int c = 0; c < 8; ++c) {
                if (c < 7) {
                    const bf16* nh = &g_Hrbf[par][0][sb][(c + 1) * 128 + skq];
                    const bf16* nl = &g_Hrbf[par][1][sb][(c + 1) * 128 + skq];
                    rh0 = *(const uint4*)nh; rh1 = *(const uint4*)(nh + 8);
                    rl0 = *(const uint4*)nl; rl1 = *(const uint4*)(nl + 8);
                }
                const unsigned bufo = (unsigned)(c & 1) * BUFB;
                {
                    unsigned boff = (c * 128 + kq2 * 32) * 2;
                    unsigned bh[4], bl[4];
                    ldsm_x4(bh[0], bh[1], bh[2], bh[3], b2h + boff);
                    ldsm_x4(bl[0], bl[1], bl[2], bl[3], b2l + boff);
#pragma unroll
                    for (int ks = 0; ks < 2; ++ks) {
                        unsigned aoff = bufo + (kq2 * 32 + ks * 16) * 2;
                        unsigned ah[4], al[4];
                        ldsm_x4(ah[0], ah[1], ah[2], ah[3], a_hi_b + aoff);
                        ldsm_x4(al[0], al[1], al[2], al[3], a_hi_b + aoff + LOB);
                        mma_bf16(acc2, ah, bh[2 * ks], bh[2 * ks + 1]);
                        mma_bf16(acc2, ah, bl[2 * ks], bl[2 * ks + 1]);
                        mma_bf16(acc2, al, bh[2 * ks], bh[2 * ks + 1]);
                    }
                }
                if (c < 7) {
                    bf16* dn = &sm[((c + 1) & 1) * 2 * ABUF + sb * ASTR + skq];
                    *(uint4*)dn = rh0; *(uint4*)(dn + 8) = rh1;
                    *(uint4*)(dn + ABUF) = rl0; *(uint4*)(dn + ABUF + 8) = rl1;
                    __syncthreads();
                }
            }
        }
        if (w >= 4) *(float4*)&red[((w - 4) * 32 + lane) * 4] = *(float4*)acc2;
        __syncthreads();
        if (w < 4) {
#pragma unroll
            for (int q = 0; q < 3; ++q) {
                float4 o = *(float4*)&red[((q * 4 + w) * 32 + lane) * 4];
                acc2[0] += o.x; acc2[1] += o.y; acc2[2] += o.z; acc2[3] += o.w;
            }
            float t0 = tanh_f(acc2[0] + xa2.x), t1 = tanh_f(acc2[1] + xa2.y);
            float t2 = tanh_f(acc2[2] + xb2.x), t3 = tanh_f(acc2[3] + xb2.y);
            float z00 = zsm[ej * 64 + r0], z01 = zsm[(ej + 1) * 64 + r0];
            float z10 = zsm[ej * 64 + r0 + 8], z11 = zsm[(ej + 1) * 64 + r0 + 8];
            float* Hn = g_H[p ^ 1];
            float n00 = z00 * h2c[0] + (1.f - z00) * t0;
            float n01 = z01 * h2c[1] + (1.f - z01) * t1;
            float n10 = z10 * h2c[2] + (1.f - z10) * t2;
            float n11 = z11 * h2c[3] + (1.f - z11) * t3;
            Hn[(colb + ej) * BB + r0] = n00;
            Hn[(colb + ej + 1) * BB + r0] = n01;
            Hn[(colb + ej) * BB + r0 + 8] = n10;
            Hn[(colb + ej + 1) * BB + r0 + 8] = n11;
            st_hilo(&g_Hbf[p ^ 1][0][r0][colb + ej], &g_Hbf[p ^ 1][1][r0][colb + ej], n00, n01);
            st_hilo(&g_Hbf[p ^ 1][0][r0 + 8][colb + ej], &g_Hbf[p ^ 1][1][r0 + 8][colb + ej], n10, n11);
        }
        __syncthreads();
        if (tid == 0) { __threadfence(); publish(&g_F2[bx * 32], (unsigned)(s + 1)); }
        p ^= 1;
    }
}

// =====================================================================
// Kernel 3: logits + softmax
// =====================================================================
__global__ __launch_bounds__(256) void out_kernel(const float* __restrict__ Whq,
                                                  const float* __restrict__ bq,
                                                  float* __restrict__ out) {
    const int b = blockIdx.x, t = threadIdx.x;
    float acc[NO];
#pragma unroll
    for (int o = 0; o < NO; o++) acc[o] = 0.f;
#pragma unroll
    for (int i = 0; i < HD / 256; i++) {
        int k = t + i * 256;
        float hv = g_H[0][k * BB + b];
        const float* wp = Whq + (size_t)k * NO;
#pragma unroll
        for (int o = 0; o < NO; o++) acc[o] += hv * wp[o];
    }
    __shared__ float part[256 * NO];
#pragma unroll
    for (int o = 0; o < NO; o++) part[t * NO + o] = acc[o];
    __syncthreads();
    __shared__ float logits[NO];
    if (t < NO) {
        float sum = bq[t];
        for (int i = 0; i < 256; i++) sum += part[i * NO + t];
        logits[t] = sum;
    }
    __syncthreads();
    if (t == 0) {
        float mx = logits[0];
#pragma unroll
        for (int o = 1; o < NO; o++) mx = fmaxf(mx, logits[o]);
        float e[NO]; float sum = 0.f;
#pragma unroll
        for (int o = 0; o < NO; o++) { e[o] = __expf(logits[o] - mx); sum += e[o]; }
        float inv = 1.0f / sum;
#pragma unroll
        for (int o = 0; o < NO; o++) out[b * NO + o] = e[o] * inv;
    }
}

// =====================================================================
extern "C" void kernel_launch(void* const* d_in, const int* in_sizes, int n_in,
                              void* d_out, int out_size) {
    const int*   inputs = (const int*)d_in[0];
    const float* emb = (const float*)d_in[1];
    const float* Wxr = (const float*)d_in[2];
    const float* Whr = (const float*)d_in[3];
    const float* br  = (const float*)d_in[4];
    const float* Wxz = (const float*)d_in[5];
    const float* Whz = (const float*)d_in[6];
    const float* bz  = (const float*)d_in[7];
    const float* Wxc = (const float*)d_in[8];
    const float* Whc = (const float*)d_in[9];
    const float* bc  = (const float*)d_in[10];
    const float* Whq = (const float*)d_in[11];
    const float* bq  = (const float*)d_in[12];
    float* out = (float*)d_out;

    static int smem_set = 0;
    if (!smem_set) {
        cudaFuncSetAttribute(gru_kernel,
                             cudaFuncAttributeMaxDynamicSharedMemorySize, GRU_SMEM);
        smem_set = 1;
    }

    reset_kernel<<<1, 256>>>();
    dim3 wg(512, 3);
    wconv_kernel<<<wg, 256>>>(Wxr, Wxz, Wxc);
    dim3 wrg(1024, 3);
    wrconv_kernel<<<wrg, 256>>>(Whr, Whz, Whc);
    dim3 pg(48, 512);
    proj_kernel<<<pg, 256>>>(inputs, emb, br, bz, bc);
    gru_kernel<<<NBLK, GTHR, GRU_SMEM>>>();
    out_kernel<<<64, 256>>>(Whq, bq, out);
}